// round 2
// baseline (speedup 1.0000x reference)
#include <cuda_runtime.h>

#define K     3
#define K2    9
#define PAD   1
#define Bn    2
#define Hn    352
#define Wn    1216
#define HW    (Hn * Wn)
#define QW    (Wn / 4)          // 304 quads per row

__device__ __forceinline__ float bilinear_sample(const float* __restrict__ img,
                                                 float py, float px) {
    float y0f = floorf(py);
    float x0f = floorf(px);
    float ly  = py - y0f;
    float lx  = px - x0f;
    int y0 = (int)y0f;
    int x0 = (int)x0f;
    int y1 = y0 + 1;
    int x1 = x0 + 1;

    bool yv0 = (y0 >= 0) & (y0 < Hn);
    bool yv1 = (y1 >= 0) & (y1 < Hn);
    bool xv0 = (x0 >= 0) & (x0 < Wn);
    bool xv1 = (x1 >= 0) & (x1 < Wn);

    float v00 = 0.f, v01 = 0.f, v10 = 0.f, v11 = 0.f;
    int base0 = y0 * Wn;
    int base1 = base0 + Wn;
    if (yv0 & xv0) v00 = __ldg(img + base0 + x0);
    if (yv0 & xv1) v01 = __ldg(img + base0 + x1);
    if (yv1 & xv0) v10 = __ldg(img + base1 + x0);
    if (yv1 & xv1) v11 = __ldg(img + base1 + x1);

    float omly = 1.f - ly;
    float omlx = 1.f - lx;
    float top = fmaf(omlx, v00, lx * v01);
    float bot = fmaf(omlx, v10, lx * v11);
    return fmaf(omly, top, ly * bot);
}

__global__ __launch_bounds__(320)
void postproc_deconv_kernel(const float* __restrict__ depth,
                            const float* __restrict__ weight,
                            const float* __restrict__ offset,
                            const float* __restrict__ wker,
                            const float* __restrict__ bias,
                            float* __restrict__ out) {
    int q = threadIdx.x;            // quad index within row
    int y = blockIdx.y;
    int b = blockIdx.z;
    if (q >= QW) return;

    int x0  = q * 4;
    int pix = y * Wn + x0;          // 16B-aligned (x0 % 4 == 0)

    const float* dplane = depth + b * HW;
    const float* wbase  = weight + b * (K2 * HW) + pix;
    const float* obase  = offset + b * (2 * K2 * HW) + pix;

    // ---- weights: 9 x float4, compute per-lane mean ----
    float4 wk4[K2];
    float4 wsum = make_float4(0.f, 0.f, 0.f, 0.f);
    #pragma unroll
    for (int k = 0; k < K2; k++) {
        float4 wv = __ldg((const float4*)(wbase + k * HW));
        wk4[k] = wv;
        wsum.x += wv.x; wsum.y += wv.y; wsum.z += wv.z; wsum.w += wv.w;
    }
    const float inv9 = 1.0f / 9.0f;
    float mean[4] = { wsum.x * inv9, wsum.y * inv9, wsum.z * inv9, wsum.w * inv9 };

    float4 d4 = __ldg((const float4*)(dplane + pix));
    float dd[4] = { d4.x, d4.y, d4.z, d4.w };

    float acc[4] = { 0.f, 0.f, 0.f, 0.f };

    #pragma unroll
    for (int k = 0; k < K2; k++) {
        int kh = k / K;
        int kw = k % K;
        float4 dy4 = __ldg((const float4*)(obase + (2 * k)     * HW));
        float4 dx4 = __ldg((const float4*)(obase + (2 * k + 1) * HW));
        float dys[4] = { dy4.x, dy4.y, dy4.z, dy4.w };
        float dxs[4] = { dx4.x, dx4.y, dx4.z, dx4.w };
        float wc = __ldg(wker + k);
        float wkk[4] = { wk4[k].x, wk4[k].y, wk4[k].z, wk4[k].w };

        float py_base = (float)(y - PAD + kh);
        float px_base = (float)(x0 - PAD + kw);
        #pragma unroll
        for (int j = 0; j < 4; j++) {
            float py = py_base + dys[j];
            float px = px_base + (float)j + dxs[j];
            float s  = bilinear_sample(dplane, py, px);
            acc[j] = fmaf(wc * (wkk[j] - mean[j]), s, acc[j]);
        }
    }

    float bb = __ldg(bias);
    float4 o4;
    o4.x = dd[0] + acc[0] + bb;
    o4.y = dd[1] + acc[1] + bb;
    o4.z = dd[2] + acc[2] + bb;
    o4.w = dd[3] + acc[3] + bb;
    *(float4*)(out + b * HW + pix) = o4;
}

extern "C" void kernel_launch(void* const* d_in, const int* in_sizes, int n_in,
                              void* d_out, int out_size) {
    const float* depth  = (const float*)d_in[0];
    const float* weight = (const float*)d_in[1];
    const float* offset = (const float*)d_in[2];
    const float* wker   = (const float*)d_in[3];
    const float* bias   = (const float*)d_in[4];
    float* out = (float*)d_out;

    dim3 block(320, 1, 1);          // 304 active quad-threads per row
    dim3 grid(1, Hn, Bn);
    postproc_deconv_kernel<<<grid, block>>>(depth, weight, offset, wker, bias, out);
}

// round 3
// speedup vs baseline: 1.3073x; 1.3073x over previous
#include <cuda_runtime.h>

#define K     3
#define K2    9
#define PAD   1
#define Bn    2
#define Hn    352
#define Wn    1216
#define HW    (Hn * Wn)

#define TX    64            // tile width  (1216 = 19 * 64)
#define TY    4             // tile height (352  = 88 * 4)

__device__ __forceinline__ float bilinear_sample(const float* __restrict__ img,
                                                 float py, float px) {
    float y0f = floorf(py);
    float x0f = floorf(px);
    float ly  = py - y0f;
    float lx  = px - x0f;
    int y0 = (int)y0f;
    int x0 = (int)x0f;
    int y1 = y0 + 1;
    int x1 = x0 + 1;

    bool yv0 = (y0 >= 0) & (y0 < Hn);
    bool yv1 = (y1 >= 0) & (y1 < Hn);
    bool xv0 = (x0 >= 0) & (x0 < Wn);
    bool xv1 = (x1 >= 0) & (x1 < Wn);

    float v00 = 0.f, v01 = 0.f, v10 = 0.f, v11 = 0.f;
    int base0 = y0 * Wn;
    int base1 = base0 + Wn;
    if (yv0 & xv0) v00 = __ldg(img + base0 + x0);
    if (yv0 & xv1) v01 = __ldg(img + base0 + x1);
    if (yv1 & xv0) v10 = __ldg(img + base1 + x0);
    if (yv1 & xv1) v11 = __ldg(img + base1 + x1);

    float omly = 1.f - ly;
    float omlx = 1.f - lx;
    float top = fmaf(omlx, v00, lx * v01);
    float bot = fmaf(omlx, v10, lx * v11);
    return fmaf(omly, top, ly * bot);
}

__global__ __launch_bounds__(TX * TY, 4)
void postproc_deconv_kernel(const float* __restrict__ depth,
                            const float* __restrict__ weight,
                            const float* __restrict__ offset,
                            const float* __restrict__ wker,
                            const float* __restrict__ bias,
                            float* __restrict__ out) {
    int x = blockIdx.x * TX + threadIdx.x;
    int y = blockIdx.y * TY + threadIdx.y;
    int b = blockIdx.z;

    int pix = y * Wn + x;
    const float* dplane = depth  + b * HW;
    const float* wbase  = weight + b * (K2 * HW) + pix;
    const float* obase  = offset + b * (2 * K2 * HW) + pix;

    // ---- 9 weights, in-register mean ----
    float wk[K2];
    float wsum = 0.f;
    #pragma unroll
    for (int k = 0; k < K2; k++) {
        wk[k] = __ldg(wbase + k * HW);
        wsum += wk[k];
    }
    float mean = wsum * (1.0f / 9.0f);

    float d = __ldg(dplane + pix);

    float acc = 0.f;
    #pragma unroll
    for (int k = 0; k < K2; k++) {
        int kh = k / K;
        int kw = k % K;
        float dy = __ldg(obase + (2 * k)     * HW);
        float dx = __ldg(obase + (2 * k + 1) * HW);
        float py = (float)(y - PAD + kh) + dy;
        float px = (float)(x - PAD + kw) + dx;
        float s  = bilinear_sample(dplane, py, px);
        float wc = __ldg(wker + k);
        acc = fmaf(wc * (wk[k] - mean), s, acc);
    }

    out[b * HW + pix] = d + acc + __ldg(bias);
}

extern "C" void kernel_launch(void* const* d_in, const int* in_sizes, int n_in,
                              void* d_out, int out_size) {
    const float* depth  = (const float*)d_in[0];
    const float* weight = (const float*)d_in[1];
    const float* offset = (const float*)d_in[2];
    const float* wker   = (const float*)d_in[3];
    const float* bias   = (const float*)d_in[4];
    float* out = (float*)d_out;

    dim3 block(TX, TY, 1);
    dim3 grid(Wn / TX, Hn / TY, Bn);
    postproc_deconv_kernel<<<grid, block>>>(depth, weight, offset, wker, bias, out);
}

// round 6
// speedup vs baseline: 1.3168x; 1.0073x over previous
#include <cuda_runtime.h>

#define K     3
#define K2    9
#define PAD   1
#define Bn    2
#define Hn    352
#define Wn    1216
#define HW    (Hn * Wn)

__device__ __forceinline__ float bilinear_sample(const float* __restrict__ img,
                                                 float py, float px) {
    float y0f = floorf(py);
    float x0f = floorf(px);
    float ly  = py - y0f;
    float lx  = px - x0f;
    int y0 = (int)y0f;
    int x0 = (int)x0f;
    int y1 = y0 + 1;
    int x1 = x0 + 1;

    bool yv0 = (y0 >= 0) & (y0 < Hn);
    bool yv1 = (y1 >= 0) & (y1 < Hn);
    bool xv0 = (x0 >= 0) & (x0 < Wn);
    bool xv1 = (x1 >= 0) & (x1 < Wn);

    float v00 = 0.f, v01 = 0.f, v10 = 0.f, v11 = 0.f;
    int base0 = y0 * Wn;
    int base1 = base0 + Wn;
    if (yv0 & xv0) v00 = __ldg(img + base0 + x0);
    if (yv0 & xv1) v01 = __ldg(img + base0 + x1);
    if (yv1 & xv0) v10 = __ldg(img + base1 + x0);
    if (yv1 & xv1) v11 = __ldg(img + base1 + x1);

    float omly = 1.f - ly;
    float omlx = 1.f - lx;
    float top = fmaf(omlx, v00, lx * v01);
    float bot = fmaf(omlx, v10, lx * v11);
    return fmaf(omly, top, ly * bot);
}

// Block (32,8): each thread handles 2 adjacent pixels (float2), tile = 64x8.
__global__ __launch_bounds__(256, 4)
void postproc_deconv_kernel(const float* __restrict__ depth,
                            const float* __restrict__ weight,
                            const float* __restrict__ offset,
                            const float* __restrict__ wker,
                            const float* __restrict__ bias,
                            float* __restrict__ out) {
    int x0 = blockIdx.x * 64 + threadIdx.x * 2;
    int y  = blockIdx.y * 8  + threadIdx.y;
    int b  = blockIdx.z;

    int pix = y * Wn + x0;                 // even -> 8B aligned
    const float* dplane = depth  + b * HW;
    const float* wbase  = weight + b * (K2 * HW) + pix;
    const float* obase  = offset + b * (2 * K2 * HW) + pix;

    // Hoist uniform conv weights + bias (L1-resident broadcast loads).
    float wc[K2];
    #pragma unroll
    for (int k = 0; k < K2; k++) wc[k] = __ldg(wker + k);
    float bb = __ldg(bias);

    // Fused accumulators: out_j = d_j + A_j - (wsum_j/9)*S_j + bias
    //   A = sum_k wc_k * wk_k * s_k
    //   S = sum_k wc_k * s_k
    //   wsum = sum_k wk_k
    float A0 = 0.f, A1 = 0.f, S0 = 0.f, S1 = 0.f, ws0 = 0.f, ws1 = 0.f;

    #pragma unroll
    for (int k = 0; k < K2; k++) {
        int kh = k / K;
        int kw = k % K;
        float2 wk2 = __ldg((const float2*)(wbase + k * HW));
        float2 dy2 = __ldg((const float2*)(obase + (2 * k)     * HW));
        float2 dx2 = __ldg((const float2*)(obase + (2 * k + 1) * HW));

        float py_base = (float)(y - PAD + kh);
        float px_base = (float)(x0 - PAD + kw);

        float s0 = bilinear_sample(dplane, py_base + dy2.x, px_base + dx2.x);
        float s1 = bilinear_sample(dplane, py_base + dy2.y, px_base + 1.f + dx2.y);

        float t0 = wc[k] * s0;
        float t1 = wc[k] * s1;
        A0 = fmaf(t0, wk2.x, A0);
        A1 = fmaf(t1, wk2.y, A1);
        S0 += t0;
        S1 += t1;
        ws0 += wk2.x;
        ws1 += wk2.y;
    }

    float2 d2 = __ldg((const float2*)(dplane + pix));
    const float inv9 = 1.0f / 9.0f;

    float2 o2;
    o2.x = d2.x + A0 - (ws0 * inv9) * S0 + bb;
    o2.y = d2.y + A1 - (ws1 * inv9) * S1 + bb;
    *(float2*)(out + b * HW + pix) = o2;
}

extern "C" void kernel_launch(void* const* d_in, const int* in_sizes, int n_in,
                              void* d_out, int out_size) {
    const float* depth  = (const float*)d_in[0];
    const float* weight = (const float*)d_in[1];
    const float* offset = (const float*)d_in[2];
    const float* wker   = (const float*)d_in[3];
    const float* bias   = (const float*)d_in[4];
    float* out = (float*)d_out;

    dim3 block(32, 8, 1);
    dim3 grid(Wn / 64, Hn / 8, Bn);
    postproc_deconv_kernel<<<grid, block>>>(depth, weight, offset, wker, bias, out);
}